// round 16
// baseline (speedup 1.0000x reference)
#include <cuda_runtime.h>
#include <cuda_fp16.h>
#include <math.h>
#include <stdint.h>

// ---------------------------------------------------------------------------
// Problem constants
// ---------------------------------------------------------------------------
#define NB    128
#define LSEQ  128
#define DIM   768
#define NF    1024
#define LOUT  126
#define NROWS (NB * LSEQ)

#define K2    1536
#define K3    2304
#define K4    3072
#define KTOT  3072
#define KC    64             // K per chunk (fp16 elems) -> 128B row
#define NCHUNK (KTOT / KC)   // 48
#define PH1   (K2 / KC)      // 24: chunks with 3 active branches
#define PH2   (K3 / KC)      // 36: chunks with 2 active branches

#define NTHR  256            // 8 warps: 4 m x 2 n, warp tile 32x32

// smem layout (bytes)
#define A_STRIDE  144                      // 64 fp16 (128B) + 16B pad
#define STAGE_A   (128 * A_STRIDE)         // 18432
#define STAGE_B1  (64 * A_STRIDE)          // 9216
#define STAGE_SZ  (STAGE_A + 3 * STAGE_B1) // 46080
#define NSTAGE    4
#define SMEM_DYN  (NSTAGE * STAGE_SZ)      // 184320

// ---------------------------------------------------------------------------
// Scratch (device globals; no allocations allowed)
// ---------------------------------------------------------------------------
__device__ __half g_X[(NROWS + 8) * DIM];
#define WTOT (NF * (K2 + K3 + K4))
__device__ __half g_W[WTOT];
__device__ float g_part[NB * 16 * 128];   // per-CTA (64-feat) sumsq partials
__device__ float g_sentv[NB * NF];        // unnormalized sentence head
__device__ int   g_cnt[NB];               // per-batch completion counters (0-init,
                                          // reset to 0 by last CTA each launch)

// ---------------------------------------------------------------------------
// Baseline-PTX helpers (sm_80-class; compile under compute_103)
// ---------------------------------------------------------------------------
static __device__ __forceinline__ uint32_t smem_u32(const void* p) {
    uint32_t a;
    asm("{ .reg .u64 t; cvta.to.shared.u64 t, %1; cvt.u32.u64 %0, t; }"
        : "=r"(a) : "l"(p));
    return a;
}

#define CP_ASYNC16(dst, src) \
    asm volatile("cp.async.cg.shared.global [%0], [%1], 16;" \
                 :: "r"(dst), "l"(src) : "memory")
#define CP_COMMIT() asm volatile("cp.async.commit_group;" ::: "memory")
#define CP_WAIT(n)  asm volatile("cp.async.wait_group %0;" :: "n"(n) : "memory")

#define LDMX4(r, addr) \
    asm volatile("ldmatrix.sync.aligned.m8n8.x4.shared.b16 {%0,%1,%2,%3}, [%4];" \
                 : "=r"((r)[0]), "=r"((r)[1]), "=r"((r)[2]), "=r"((r)[3]) \
                 : "r"(addr))

#define MMA16816(d, a, b0v, b1v) \
    asm volatile("mma.sync.aligned.m16n8k16.row.col.f32.f16.f16.f32 " \
                 "{%0,%1,%2,%3},{%4,%5,%6,%7},{%8,%9},{%0,%1,%2,%3};" \
                 : "+f"((d)[0]), "+f"((d)[1]), "+f"((d)[2]), "+f"((d)[3]) \
                 : "r"((a)[0]), "r"((a)[1]), "r"((a)[2]), "r"((a)[3]), \
                   "r"(b0v), "r"(b1v))

// ---------------------------------------------------------------------------
// Prep: fp32 -> fp16 (X and W in one kernel)
// ---------------------------------------------------------------------------
__global__ void cvt_all_kernel(const float* __restrict__ X,
                               const float* __restrict__ W2,
                               const float* __restrict__ W3,
                               const float* __restrict__ W4) {
    const int nx2 = (NROWS + 8) * DIM / 2;
    const int limx2 = NROWS * DIM / 2;
    const int nw2 = WTOT / 2;
    const int total = nx2 + nw2;
    __half2* dX = (__half2*)g_X;
    __half2* dW = (__half2*)g_W;
    for (int i = blockIdx.x * blockDim.x + threadIdx.x; i < total;
         i += gridDim.x * blockDim.x) {
        if (i < nx2) {
            float2 v = (i < limx2) ? *(const float2*)(X + 2 * i)
                                   : make_float2(0.f, 0.f);
            dX[i] = __floats2half2_rn(v.x, v.y);
        } else {
            int k = i - nx2;
            int j = 2 * k;
            const float* src;
            if (j < NF * K2)             src = W2 + j;
            else if (j < NF * (K2 + K3)) src = W3 + (j - NF * K2);
            else                         src = W4 + (j - NF * (K2 + K3));
            float2 v = *(const float2*)src;
            dW[k] = __floats2half2_rn(v.x, v.y);
        }
    }
}

// ---------------------------------------------------------------------------
// Per-chunk compute body (frozen best config). NBR = active branches.
// ---------------------------------------------------------------------------
template<int NBR>
static __device__ __forceinline__ void do_chunk(
    uint32_t sA, int lane, int wm, int wn, float (&acc)[3][2][4][4])
{
    uint32_t afr[2][4][4];
    #pragma unroll
    for (int mt = 0; mt < 2; ++mt)
        #pragma unroll
        for (int ks = 0; ks < 4; ++ks) {
            int m = wm * 32 + mt * 16 + (lane & 7) + ((lane >> 3) & 1) * 8;
            int k = ks * 16 + (lane >> 4) * 8;
            LDMX4(afr[mt][ks], sA + m * A_STRIDE + k * 2);
        }

    #pragma unroll
    for (int biR = 0; biR < NBR; ++biR) {
        const int bi = 3 - NBR + biR;
        const uint32_t sB = sA + STAGE_A + bi * STAGE_B1;
        uint32_t bfr[2][4][4];
        #pragma unroll
        for (int np = 0; np < 2; ++np)
            #pragma unroll
            for (int ks = 0; ks < 4; ++ks) {
                int n = wn * 32 + np * 16 + (lane & 7) + (lane >> 4) * 8;
                int k = ks * 16 + ((lane >> 3) & 1) * 8;
                LDMX4(bfr[np][ks], sB + n * A_STRIDE + k * 2);
            }
        #pragma unroll
        for (int ks = 0; ks < 4; ++ks)
            #pragma unroll
            for (int mt = 0; mt < 2; ++mt)
                #pragma unroll
                for (int np = 0; np < 2; ++np)
                    #pragma unroll
                    for (int sub = 0; sub < 2; ++sub) {
                        const int nt = np * 2 + sub;
                        MMA16816(acc[bi][mt][nt], afr[mt][ks],
                                 bfr[np][ks][sub * 2], bfr[np][ks][sub * 2 + 1]);
                    }
    }
}

// ---------------------------------------------------------------------------
// Fused conv — frozen best mainloop (646-648 us) + fused L2-normalize:
// the LAST CTA of each batch (16 per batch, tracked by g_cnt) re-reads the
// 16 sumsq partials and scales the whole batch's output block in place.
// ---------------------------------------------------------------------------
__global__ __launch_bounds__(NTHR, 1)
void conv_tc(const float* __restrict__ b2, const float* __restrict__ b3,
             const float* __restrict__ b4, float* __restrict__ out)
{
    extern __shared__ char sm[];
    const uint32_t sb = smem_u32(sm);
    __shared__ float s_bias[3][64];
    __shared__ float s_r[128];
    __shared__ int   s_last;

    const int tid  = threadIdx.x;
    const int lane = tid & 31;
    const int wid  = tid >> 5;
    const int wm   = wid & 3;
    const int wn   = wid >> 2;
    const int f0   = blockIdx.x * 64;
    const int b    = blockIdx.y;

    if (tid < 64) {
        s_bias[0][tid] = b2[f0 + tid];
        s_bias[1][tid] = b3[f0 + tid];
        s_bias[2][tid] = b4[f0 + tid];
    }

    const int    Ks[3]    = {K2, K3, K4};
    const size_t wbase[3] = {0, (size_t)NF * K2, (size_t)NF * (K2 + K3)};
    const size_t xbase    = (size_t)b * LSEQ * DIM;

    float acc[3][2][4][4];
    #pragma unroll
    for (int bi = 0; bi < 3; ++bi)
        #pragma unroll
        for (int mt = 0; mt < 2; ++mt)
            #pragma unroll
            for (int nt = 0; nt < 4; ++nt)
                #pragma unroll
                for (int q = 0; q < 4; ++q) acc[bi][mt][nt][q] = 0.f;

    auto issue_loads = [&](int st, int ch) {
        const int j0 = ch * KC;
        const uint32_t sst = sb + st * STAGE_SZ;
        #pragma unroll
        for (int p = 0; p < 4; ++p) {
            int idx = tid + p * NTHR;
            int row = idx >> 3, c = idx & 7;
            const __half* src = g_X + xbase + (size_t)row * DIM + j0 + c * 8;
            CP_ASYNC16(sst + row * A_STRIDE + c * 16, src);
        }
        #pragma unroll
        for (int bi = 0; bi < 3; ++bi) {
            if (j0 >= Ks[bi]) continue;
            const uint32_t sB = sst + STAGE_A + bi * STAGE_B1;
            #pragma unroll
            for (int p = 0; p < 2; ++p) {
                int idx = tid + p * NTHR;
                int row = idx >> 3, c = idx & 7;
                const __half* src = g_W + wbase[bi] + (size_t)(f0 + row) * Ks[bi] + j0 + c * 8;
                CP_ASYNC16(sB + row * A_STRIDE + c * 16, src);
            }
        }
        CP_COMMIT();
    };

    auto step_pre = [&](int ch) {
        if (ch + 2 < NCHUNK) { issue_loads((ch + 2) % NSTAGE, ch + 2); CP_WAIT(2); }
        else if (ch + 1 < NCHUNK) { CP_WAIT(1); }
        else { CP_WAIT(0); }
        __syncthreads();
    };

    issue_loads(0, 0);
    issue_loads(1, 1);

    for (int ch = 0; ch < PH1; ++ch) {
        step_pre(ch);
        do_chunk<3>(sb + (ch % NSTAGE) * STAGE_SZ, lane, wm, wn, acc);
    }
    for (int ch = PH1; ch < PH2; ++ch) {
        step_pre(ch);
        do_chunk<2>(sb + (ch % NSTAGE) * STAGE_SZ, lane, wm, wn, acc);
    }
    for (int ch = PH2; ch < NCHUNK; ++ch) {
        step_pre(ch);
        do_chunk<1>(sb + (ch % NSTAGE) * STAGE_SZ, lane, wm, wn, acc);
    }

    // ---- epilogue: bias+relu+branch max -> smem [64f][132] -> coalesced out ----
    float* sOut = (float*)sm;
    #pragma unroll
    for (int mt = 0; mt < 2; ++mt)
        #pragma unroll
        for (int nt = 0; nt < 4; ++nt) {
            int mb = wm * 32 + mt * 16 + (lane >> 2);
            int n0 = wn * 32 + nt * 8 + (lane & 3) * 2;
            #pragma unroll
            for (int h = 0; h < 2; ++h) {
                int l = mb + h * 8;
                #pragma unroll
                for (int q = 0; q < 2; ++q) {
                    int fl = n0 + q;
                    float va = fmaxf(acc[0][mt][nt][h * 2 + q] + s_bias[0][fl], 0.f);
                    float vb = fmaxf(acc[1][mt][nt][h * 2 + q] + s_bias[1][fl], 0.f);
                    float vc = fmaxf(acc[2][mt][nt][h * 2 + q] + s_bias[2][fl], 0.f);
                    float v;
                    if (l < LOUT - 2)       v = fmaxf(fmaxf(va, vb), vc);
                    else if (l == LOUT - 2) v = fmaxf(va, vb);
                    else                    v = va;     // l >= 126 not stored
                    sOut[fl * 132 + l] = v;
                }
            }
        }
    __syncthreads();

    // partial sum-of-squares over this CTA's 64 features
    if (tid < LOUT) {
        float s = 0.f;
        #pragma unroll 8
        for (int f = 0; f < 64; ++f) {
            float v = sOut[f * 132 + tid];
            s += v * v;
        }
        g_part[((size_t)b * 16 + blockIdx.x) * 128 + tid] = s;
    }

    for (int idx = tid; idx < 64 * LOUT; idx += NTHR) {
        int f = idx / LOUT, l = idx % LOUT;
        out[((size_t)b * NF + f0 + f) * LOUT + l] = sOut[f * 132 + l];
    }

    // ---- fused norm: last CTA of this batch scales the whole batch ----
    __threadfence();                 // make out + g_part writes visible
    __syncthreads();                 // all threads' stores issued before atomic
    if (tid == 0) {
        int old = atomicAdd(&g_cnt[b], 1);
        s_last = (old == 15) ? 1 : 0;
    }
    __syncthreads();
    if (s_last) {
        if (tid < LOUT) {
            float s = 0.f;
            #pragma unroll
            for (int g = 0; g < 16; ++g)
                s += g_part[((size_t)b * 16 + g) * 128 + tid];
            s_r[tid] = 1.f / fmaxf(sqrtf(s), 1e-12f);
        }
        __syncthreads();
        float* base = out + (size_t)b * NF * LOUT;
        for (int idx = tid; idx < NF * LOUT; idx += NTHR) {
            int f = idx / LOUT;
            int l = idx - f * LOUT;
            base[idx] *= s_r[l];
        }
        if (tid == 0) g_cnt[b] = 0;   // reset for next graph replay
    }
}

// ---------------------------------------------------------------------------
// Sentence head, stage 1: tiled GEMM vals = S @ Wp^T + bp.
// ---------------------------------------------------------------------------
__global__ void sent_mm(const float* __restrict__ S, const float* __restrict__ Wp,
                        const float* __restrict__ bp)
{
    extern __shared__ float sS[];               // 16 x 768 fp32 = 48 KB
    const int tid  = threadIdx.x;
    const int lane = tid & 31;
    const int wid  = tid >> 5;
    const int fg   = blockIdx.x;
    const int bg   = blockIdx.y;

    {
        const float4* src = (const float4*)(S + (size_t)bg * 16 * DIM);
        float4* dst = (float4*)sS;
        for (int i = tid; i < 16 * DIM / 4; i += 256) dst[i] = src[i];
    }
    __syncthreads();

    for (int ff = wid; ff < 128; ff += 8) {
        const int f = fg * 128 + ff;
        const float4* w4 = (const float4*)(Wp + (size_t)f * DIM);
        float4 wf[6];
        #pragma unroll
        for (int j = 0; j < 6; ++j) wf[j] = w4[lane + j * 32];
        const float bias = bp[f];
        #pragma unroll 4
        for (int bb = 0; bb < 16; ++bb) {
            const float* sp = sS + bb * DIM;
            float a = 0.f;
            #pragma unroll
            for (int j = 0; j < 6; ++j) {
                float4 sv = *(const float4*)(sp + lane * 4 + j * 128);
                a += wf[j].x * sv.x + wf[j].y * sv.y + wf[j].z * sv.z + wf[j].w * sv.w;
            }
            #pragma unroll
            for (int o = 16; o > 0; o >>= 1) a += __shfl_down_sync(0xffffffffu, a, o);
            if (lane == 0) g_sentv[(size_t)(bg * 16 + bb) * NF + f] = a + bias;
        }
    }
}

// ---------------------------------------------------------------------------
// Sentence head, stage 2: per-batch l2 normalize.
// ---------------------------------------------------------------------------
__global__ void sent_norm(float* __restrict__ out)
{
    const int b = blockIdx.x;
    const int tid = threadIdx.x;
    __shared__ float red[256];
    float s = 0.f;
    for (int f = tid; f < NF; f += 256) {
        float v = g_sentv[(size_t)b * NF + f];
        s += v * v;
    }
    red[tid] = s;
    __syncthreads();
    for (int o = 128; o > 0; o >>= 1) {
        if (tid < o) red[tid] += red[tid + o];
        __syncthreads();
    }
    const float n = fmaxf(sqrtf(red[0]), 1e-12f);
    for (int f = tid; f < NF; f += 256)
        out[(size_t)b * NF + f] = g_sentv[(size_t)b * NF + f] / n;
}

// ---------------------------------------------------------------------------
// Launch: two-stream fork/join inside the captured graph.
//   main stream: cvt_all -> conv_tc (norm fused inside)
//   side stream: sent_mm -> sent_norm   (independent; overlaps cvt+conv)
// ---------------------------------------------------------------------------
extern "C" void kernel_launch(void* const* d_in, const int* in_sizes, int n_in,
                              void* d_out, int out_size)
{
    const float* X  = (const float*)d_in[0];
    const float* S  = (const float*)d_in[1];
    const float* W2 = (const float*)d_in[2];
    const float* b2 = (const float*)d_in[3];
    const float* W3 = (const float*)d_in[4];
    const float* b3 = (const float*)d_in[5];
    const float* W4 = (const float*)d_in[6];
    const float* b4 = (const float*)d_in[7];
    const float* Wp = (const float*)d_in[8];
    const float* bp = (const float*)d_in[9];
    float* out = (float*)d_out;

    static int inited = 0;
    static cudaStream_t s2;
    static cudaEvent_t eFork, eJoin;
    if (!inited) {
        cudaFuncSetAttribute(conv_tc, cudaFuncAttributeMaxDynamicSharedMemorySize, SMEM_DYN);
        cudaStreamCreateWithFlags(&s2, cudaStreamNonBlocking);
        cudaEventCreateWithFlags(&eFork, cudaEventDisableTiming);
        cudaEventCreateWithFlags(&eJoin, cudaEventDisableTiming);
        inited = 1;
    }

    // Fork: side stream joins the capture via event dependency.
    cudaEventRecord(eFork, 0);
    cudaStreamWaitEvent(s2, eFork, 0);

    // Side stream: sentence head (independent of conv pipeline).
    sent_mm<<<dim3(8, 8), 256, 16 * DIM * sizeof(float), s2>>>(S, Wp, bp);
    sent_norm<<<NB, 256, 0, s2>>>(out + (size_t)NB * NF * LOUT);
    cudaEventRecord(eJoin, s2);

    // Main stream: conv pipeline (norm fused into conv_tc).
    cvt_all_kernel<<<1024, 256>>>(X, W2, W3, W4);
    conv_tc<<<dim3(16, NB), NTHR, SMEM_DYN>>>(b2, b3, b4, out);

    // Join: main stream waits for the sentence head before graph end.
    cudaStreamWaitEvent(0, eJoin, 0);
}

// round 17
// speedup vs baseline: 1.0886x; 1.0886x over previous
#include <cuda_runtime.h>
#include <cuda_fp16.h>
#include <math.h>
#include <stdint.h>

// ---------------------------------------------------------------------------
// Problem constants
// ---------------------------------------------------------------------------
#define NB    128
#define LSEQ  128
#define DIM   768
#define NF    1024
#define LOUT  126
#define NROWS (NB * LSEQ)

#define K2    1536
#define K3    2304
#define K4    3072
#define KTOT  3072
#define KC    64             // K per chunk (fp16 elems) -> 128B row
#define NCHUNK (KTOT / KC)   // 48
#define PH1   (K2 / KC)      // 24: chunks with 3 active branches
#define PH2   (K3 / KC)      // 36: chunks with 2 active branches

#define NTHR  256            // 8 warps: 4 m x 2 n, warp tile 32x32

// smem layout (bytes)
#define A_STRIDE  144                      // 64 fp16 (128B) + 16B pad
#define STAGE_A   (128 * A_STRIDE)         // 18432
#define STAGE_B1  (64 * A_STRIDE)          // 9216
#define STAGE_SZ  (STAGE_A + 3 * STAGE_B1) // 46080
#define NSTAGE    4
#define SMEM_DYN  (NSTAGE * STAGE_SZ)      // 184320

// ---------------------------------------------------------------------------
// Scratch (device globals; no allocations allowed)
// ---------------------------------------------------------------------------
__device__ __half g_X[(NROWS + 8) * DIM];
#define WTOT (NF * (K2 + K3 + K4))
__device__ __half g_W[WTOT];
__device__ float g_part[NB * 16 * 128];   // per-CTA (64-feat) sumsq partials
__device__ float g_sentv[NB * NF];        // unnormalized sentence head

// ---------------------------------------------------------------------------
// Baseline-PTX helpers (sm_80-class; compile under compute_103)
// ---------------------------------------------------------------------------
static __device__ __forceinline__ uint32_t smem_u32(const void* p) {
    uint32_t a;
    asm("{ .reg .u64 t; cvta.to.shared.u64 t, %1; cvt.u32.u64 %0, t; }"
        : "=r"(a) : "l"(p));
    return a;
}

#define CP_ASYNC16(dst, src) \
    asm volatile("cp.async.cg.shared.global [%0], [%1], 16;" \
                 :: "r"(dst), "l"(src) : "memory")
#define CP_COMMIT() asm volatile("cp.async.commit_group;" ::: "memory")
#define CP_WAIT(n)  asm volatile("cp.async.wait_group %0;" :: "n"(n) : "memory")

#define LDMX4(r, addr) \
    asm volatile("ldmatrix.sync.aligned.m8n8.x4.shared.b16 {%0,%1,%2,%3}, [%4];" \
                 : "=r"((r)[0]), "=r"((r)[1]), "=r"((r)[2]), "=r"((r)[3]) \
                 : "r"(addr))

#define MMA16816(d, a, b0v, b1v) \
    asm volatile("mma.sync.aligned.m16n8k16.row.col.f32.f16.f16.f32 " \
                 "{%0,%1,%2,%3},{%4,%5,%6,%7},{%8,%9},{%0,%1,%2,%3};" \
                 : "+f"((d)[0]), "+f"((d)[1]), "+f"((d)[2]), "+f"((d)[3]) \
                 : "r"((a)[0]), "r"((a)[1]), "r"((a)[2]), "r"((a)[3]), \
                   "r"(b0v), "r"(b1v))

// ---------------------------------------------------------------------------
// Prep: fp32 -> fp16, float4-vectorized (X and W in one kernel).
// Element values/rounding identical to the scalar version.
// ---------------------------------------------------------------------------
__global__ void cvt_all_kernel(const float* __restrict__ X,
                               const float* __restrict__ W2,
                               const float* __restrict__ W3,
                               const float* __restrict__ W4) {
    const int nx4 = (NROWS + 8) * DIM / 4;   // groups of 4 floats
    const int limx4 = NROWS * DIM / 4;
    const int nw4 = WTOT / 4;
    const int total = nx4 + nw4;
    __half2* dX = (__half2*)g_X;
    __half2* dW = (__half2*)g_W;
    for (int i = blockIdx.x * blockDim.x + threadIdx.x; i < total;
         i += gridDim.x * blockDim.x) {
        if (i < nx4) {
            float4 v = (i < limx4) ? *(const float4*)(X + 4 * (size_t)i)
                                   : make_float4(0.f, 0.f, 0.f, 0.f);
            dX[2 * i]     = __floats2half2_rn(v.x, v.y);
            dX[2 * i + 1] = __floats2half2_rn(v.z, v.w);
        } else {
            int k = i - nx4;
            int j = 4 * k;
            const float* src;
            if (j < NF * K2)             src = W2 + j;
            else if (j < NF * (K2 + K3)) src = W3 + (j - NF * K2);
            else                         src = W4 + (j - NF * (K2 + K3));
            float4 v = *(const float4*)src;
            dW[2 * k]     = __floats2half2_rn(v.x, v.y);
            dW[2 * k + 1] = __floats2half2_rn(v.z, v.w);
        }
    }
}

// ---------------------------------------------------------------------------
// Per-chunk compute body (frozen best config). NBR = active branches.
// ---------------------------------------------------------------------------
template<int NBR>
static __device__ __forceinline__ void do_chunk(
    uint32_t sA, int lane, int wm, int wn, float (&acc)[3][2][4][4])
{
    uint32_t afr[2][4][4];
    #pragma unroll
    for (int mt = 0; mt < 2; ++mt)
        #pragma unroll
        for (int ks = 0; ks < 4; ++ks) {
            int m = wm * 32 + mt * 16 + (lane & 7) + ((lane >> 3) & 1) * 8;
            int k = ks * 16 + (lane >> 4) * 8;
            LDMX4(afr[mt][ks], sA + m * A_STRIDE + k * 2);
        }

    #pragma unroll
    for (int biR = 0; biR < NBR; ++biR) {
        const int bi = 3 - NBR + biR;
        const uint32_t sB = sA + STAGE_A + bi * STAGE_B1;
        uint32_t bfr[2][4][4];
        #pragma unroll
        for (int np = 0; np < 2; ++np)
            #pragma unroll
            for (int ks = 0; ks < 4; ++ks) {
                int n = wn * 32 + np * 16 + (lane & 7) + (lane >> 4) * 8;
                int k = ks * 16 + ((lane >> 3) & 1) * 8;
                LDMX4(bfr[np][ks], sB + n * A_STRIDE + k * 2);
            }
        #pragma unroll
        for (int ks = 0; ks < 4; ++ks)
            #pragma unroll
            for (int mt = 0; mt < 2; ++mt)
                #pragma unroll
                for (int np = 0; np < 2; ++np)
                    #pragma unroll
                    for (int sub = 0; sub < 2; ++sub) {
                        const int nt = np * 2 + sub;
                        MMA16816(acc[bi][mt][nt], afr[mt][ks],
                                 bfr[np][ks][sub * 2], bfr[np][ks][sub * 2 + 1]);
                    }
    }
}

// ---------------------------------------------------------------------------
// Fused conv — frozen best configuration (646-648 us, tensor 59%).
// (R15 source, unmodified.)
// ---------------------------------------------------------------------------
__global__ __launch_bounds__(NTHR, 1)
void conv_tc(const float* __restrict__ b2, const float* __restrict__ b3,
             const float* __restrict__ b4, float* __restrict__ out)
{
    extern __shared__ char sm[];
    const uint32_t sb = smem_u32(sm);
    __shared__ float s_bias[3][64];

    const int tid  = threadIdx.x;
    const int lane = tid & 31;
    const int wid  = tid >> 5;
    const int wm   = wid & 3;
    const int wn   = wid >> 2;
    const int f0   = blockIdx.x * 64;
    const int b    = blockIdx.y;

    if (tid < 64) {
        s_bias[0][tid] = b2[f0 + tid];
        s_bias[1][tid] = b3[f0 + tid];
        s_bias[2][tid] = b4[f0 + tid];
    }

    const int    Ks[3]    = {K2, K3, K4};
    const size_t wbase[3] = {0, (size_t)NF * K2, (size_t)NF * (K2 + K3)};
    const size_t xbase    = (size_t)b * LSEQ * DIM;

    float acc[3][2][4][4];
    #pragma unroll
    for (int bi = 0; bi < 3; ++bi)
        #pragma unroll
        for (int mt = 0; mt < 2; ++mt)
            #pragma unroll
            for (int nt = 0; nt < 4; ++nt)
                #pragma unroll
                for (int q = 0; q < 4; ++q) acc[bi][mt][nt][q] = 0.f;

    auto issue_loads = [&](int st, int ch) {
        const int j0 = ch * KC;
        const uint32_t sst = sb + st * STAGE_SZ;
        #pragma unroll
        for (int p = 0; p < 4; ++p) {
            int idx = tid + p * NTHR;
            int row = idx >> 3, c = idx & 7;
            const __half* src = g_X + xbase + (size_t)row * DIM + j0 + c * 8;
            CP_ASYNC16(sst + row * A_STRIDE + c * 16, src);
        }
        #pragma unroll
        for (int bi = 0; bi < 3; ++bi) {
            if (j0 >= Ks[bi]) continue;
            const uint32_t sB = sst + STAGE_A + bi * STAGE_B1;
            #pragma unroll
            for (int p = 0; p < 2; ++p) {
                int idx = tid + p * NTHR;
                int row = idx >> 3, c = idx & 7;
                const __half* src = g_W + wbase[bi] + (size_t)(f0 + row) * Ks[bi] + j0 + c * 8;
                CP_ASYNC16(sB + row * A_STRIDE + c * 16, src);
            }
        }
        CP_COMMIT();
    };

    auto step_pre = [&](int ch) {
        if (ch + 2 < NCHUNK) { issue_loads((ch + 2) % NSTAGE, ch + 2); CP_WAIT(2); }
        else if (ch + 1 < NCHUNK) { CP_WAIT(1); }
        else { CP_WAIT(0); }
        __syncthreads();
    };

    issue_loads(0, 0);
    issue_loads(1, 1);

    for (int ch = 0; ch < PH1; ++ch) {
        step_pre(ch);
        do_chunk<3>(sb + (ch % NSTAGE) * STAGE_SZ, lane, wm, wn, acc);
    }
    for (int ch = PH1; ch < PH2; ++ch) {
        step_pre(ch);
        do_chunk<2>(sb + (ch % NSTAGE) * STAGE_SZ, lane, wm, wn, acc);
    }
    for (int ch = PH2; ch < NCHUNK; ++ch) {
        step_pre(ch);
        do_chunk<1>(sb + (ch % NSTAGE) * STAGE_SZ, lane, wm, wn, acc);
    }

    // ---- epilogue: bias+relu+branch max -> smem [64f][132] -> coalesced out ----
    float* sOut = (float*)sm;
    #pragma unroll
    for (int mt = 0; mt < 2; ++mt)
        #pragma unroll
        for (int nt = 0; nt < 4; ++nt) {
            int mb = wm * 32 + mt * 16 + (lane >> 2);
            int n0 = wn * 32 + nt * 8 + (lane & 3) * 2;
            #pragma unroll
            for (int h = 0; h < 2; ++h) {
                int l = mb + h * 8;
                #pragma unroll
                for (int q = 0; q < 2; ++q) {
                    int fl = n0 + q;
                    float va = fmaxf(acc[0][mt][nt][h * 2 + q] + s_bias[0][fl], 0.f);
                    float vb = fmaxf(acc[1][mt][nt][h * 2 + q] + s_bias[1][fl], 0.f);
                    float vc = fmaxf(acc[2][mt][nt][h * 2 + q] + s_bias[2][fl], 0.f);
                    float v;
                    if (l < LOUT - 2)       v = fmaxf(fmaxf(va, vb), vc);
                    else if (l == LOUT - 2) v = fmaxf(va, vb);
                    else                    v = va;     // l >= 126 not stored
                    sOut[fl * 132 + l] = v;
                }
            }
        }
    __syncthreads();

    // partial sum-of-squares over this CTA's 64 features (fused norm pass 1)
    if (tid < LOUT) {
        float s = 0.f;
        #pragma unroll 8
        for (int f = 0; f < 64; ++f) {
            float v = sOut[f * 132 + tid];
            s += v * v;
        }
        g_part[((size_t)b * 16 + blockIdx.x) * 128 + tid] = s;
    }

    for (int idx = tid; idx < 64 * LOUT; idx += NTHR) {
        int f = idx / LOUT, l = idx % LOUT;
        out[((size_t)b * NF + f0 + f) * LOUT + l] = sOut[f * 132 + l];
    }
}

// ---------------------------------------------------------------------------
// norm_scale: reduce 16 partials -> rsqrt -> scale. Grid (8, 128), block 128.
// ---------------------------------------------------------------------------
__global__ void norm_scale(float* __restrict__ out) {
    const int fg = blockIdx.x, b = blockIdx.y;
    const int l = threadIdx.x;
    if (l >= LOUT) return;
    float s = 0.f;
    #pragma unroll
    for (int g = 0; g < 16; ++g) s += g_part[((size_t)b * 16 + g) * 128 + l];
    const float r = 1.f / fmaxf(sqrtf(s), 1e-12f);
    float* base = out + ((size_t)b * NF + fg * 128) * LOUT + l;
    #pragma unroll 8
    for (int f = 0; f < 128; ++f)
        base[(size_t)f * LOUT] *= r;
}

// ---------------------------------------------------------------------------
// Sentence head, stage 1: tiled GEMM vals = S @ Wp^T + bp.
// ---------------------------------------------------------------------------
__global__ void sent_mm(const float* __restrict__ S, const float* __restrict__ Wp,
                        const float* __restrict__ bp)
{
    extern __shared__ float sS[];               // 16 x 768 fp32 = 48 KB
    const int tid  = threadIdx.x;
    const int lane = tid & 31;
    const int wid  = tid >> 5;
    const int fg   = blockIdx.x;
    const int bg   = blockIdx.y;

    {
        const float4* src = (const float4*)(S + (size_t)bg * 16 * DIM);
        float4* dst = (float4*)sS;
        for (int i = tid; i < 16 * DIM / 4; i += 256) dst[i] = src[i];
    }
    __syncthreads();

    for (int ff = wid; ff < 128; ff += 8) {
        const int f = fg * 128 + ff;
        const float4* w4 = (const float4*)(Wp + (size_t)f * DIM);
        float4 wf[6];
        #pragma unroll
        for (int j = 0; j < 6; ++j) wf[j] = w4[lane + j * 32];
        const float bias = bp[f];
        #pragma unroll 4
        for (int bb = 0; bb < 16; ++bb) {
            const float* sp = sS + bb * DIM;
            float a = 0.f;
            #pragma unroll
            for (int j = 0; j < 6; ++j) {
                float4 sv = *(const float4*)(sp + lane * 4 + j * 128);
                a += wf[j].x * sv.x + wf[j].y * sv.y + wf[j].z * sv.z + wf[j].w * sv.w;
            }
            #pragma unroll
            for (int o = 16; o > 0; o >>= 1) a += __shfl_down_sync(0xffffffffu, a, o);
            if (lane == 0) g_sentv[(size_t)(bg * 16 + bb) * NF + f] = a + bias;
        }
    }
}

// ---------------------------------------------------------------------------
// Sentence head, stage 2: per-batch l2 normalize.
// ---------------------------------------------------------------------------
__global__ void sent_norm(float* __restrict__ out)
{
    const int b = blockIdx.x;
    const int tid = threadIdx.x;
    __shared__ float red[256];
    float s = 0.f;
    for (int f = tid; f < NF; f += 256) {
        float v = g_sentv[(size_t)b * NF + f];
        s += v * v;
    }
    red[tid] = s;
    __syncthreads();
    for (int o = 128; o > 0; o >>= 1) {
        if (tid < o) red[tid] += red[tid + o];
        __syncthreads();
    }
    const float n = fmaxf(sqrtf(red[0]), 1e-12f);
    for (int f = tid; f < NF; f += 256)
        out[(size_t)b * NF + f] = g_sentv[(size_t)b * NF + f] / n;
}

// ---------------------------------------------------------------------------
// Launch: two-stream fork/join inside the captured graph.
//   main stream: cvt_all -> conv_tc -> norm_scale
//   side stream: sent_mm -> sent_norm   (independent; overlaps cvt+conv)
// ---------------------------------------------------------------------------
extern "C" void kernel_launch(void* const* d_in, const int* in_sizes, int n_in,
                              void* d_out, int out_size)
{
    const float* X  = (const float*)d_in[0];
    const float* S  = (const float*)d_in[1];
    const float* W2 = (const float*)d_in[2];
    const float* b2 = (const float*)d_in[3];
    const float* W3 = (const float*)d_in[4];
    const float* b3 = (const float*)d_in[5];
    const float* W4 = (const float*)d_in[6];
    const float* b4 = (const float*)d_in[7];
    const float* Wp = (const float*)d_in[8];
    const float* bp = (const float*)d_in[9];
    float* out = (float*)d_out;

    static int inited = 0;
    static cudaStream_t s2;
    static cudaEvent_t eFork, eJoin;
    if (!inited) {
        cudaFuncSetAttribute(conv_tc, cudaFuncAttributeMaxDynamicSharedMemorySize, SMEM_DYN);
        cudaStreamCreateWithFlags(&s2, cudaStreamNonBlocking);
        cudaEventCreateWithFlags(&eFork, cudaEventDisableTiming);
        cudaEventCreateWithFlags(&eJoin, cudaEventDisableTiming);
        inited = 1;
    }

    // Fork: side stream joins the capture via event dependency.
    cudaEventRecord(eFork, 0);
    cudaStreamWaitEvent(s2, eFork, 0);

    // Side stream: sentence head (independent of conv pipeline).
    sent_mm<<<dim3(8, 8), 256, 16 * DIM * sizeof(float), s2>>>(S, Wp, bp);
    sent_norm<<<NB, 256, 0, s2>>>(out + (size_t)NB * NF * LOUT);
    cudaEventRecord(eJoin, s2);

    // Main stream: conv pipeline.
    cvt_all_kernel<<<1024, 256>>>(X, W2, W3, W4);
    conv_tc<<<dim3(16, NB), NTHR, SMEM_DYN>>>(b2, b3, b4, out);
    norm_scale<<<dim3(8, NB), 128>>>(out);

    // Join: main stream waits for the sentence head before graph end.
    cudaStreamWaitEvent(0, eJoin, 0);
}